// round 1
// baseline (speedup 1.0000x reference)
#include <cuda_runtime.h>

// Problem constants
constexpr int B = 512, T = 365, C = 10, P = 64;
constexpr int K = T * C;          // 3650
constexpr int BPB = 4;            // samples per block in dist kernel
constexpr int NBLK = B / BPB;     // 128
constexpr int NTHR = 256;         // 8 warps -> 8 prototypes per warp
constexpr int TP = T + 3;         // padded mask row (368)

// Output layout (flattened tuple, all float32):
// [output_seq BKC][input_seq BKC][distances BP][indices B][label B][mask BT]
constexpr int O1 = B * K;             // input_seq
constexpr int O2 = O1 + B * K;        // distances
constexpr int O3 = O2 + B * P;        // indices
constexpr int O4 = O3 + B;            // label
constexpr int O5 = O4 + B;            // mask

__device__ int   g_idx[B];        // argmin indices for gather kernel
__device__ float g_q[P * T];      // q[p,t] = sum_c proto[p,t,c]^2

// ---------------------------------------------------------------------------
// Kernel 0: precompute q[p,t] = sum_c proto^2
// ---------------------------------------------------------------------------
__global__ void q_kernel(const float* __restrict__ proto) {
    int i = blockIdx.x * blockDim.x + threadIdx.x;
    if (i < P * T) {
        const float* pr = proto + (size_t)i * C;
        float s = 0.0f;
#pragma unroll
        for (int c = 0; c < C; c++) { float v = pr[c]; s = fmaf(v, v, s); }
        g_q[i] = s;
    }
}

// ---------------------------------------------------------------------------
// Kernel 1: distances + argmin. One block = 4 samples, all 64 prototypes.
// Each warp owns 8 prototypes; each lane strides the K dim.
// dist = x2[b] - 2*sum(mx * p) + sum_t(m[t] * q[p,t])
// ---------------------------------------------------------------------------
__global__ __launch_bounds__(NTHR) void dist_kernel(
    const float* __restrict__ x, const float* __restrict__ mask,
    const float* __restrict__ proto, float* __restrict__ out) {
    extern __shared__ float sm[];
    float* xs  = sm;                   // [BPB][K]  mask-premultiplied x
    float* mk  = xs + BPB * K;         // [BPB][TP] mask rows
    float* ds  = mk + BPB * TP;        // [BPB][P]  distances
    float* x2s = ds + BPB * P;         // [BPB]     x2 per sample

    const int b0  = blockIdx.x * BPB;
    const int tid = threadIdx.x;

    // Load mask rows
    for (int i = tid; i < BPB * T; i += NTHR) {
        int j = i / T, t = i - j * T;
        mk[j * TP + t] = mask[(size_t)(b0 + j) * T + t];
    }
    __syncthreads();

    // Load x, premultiplied by binary mask
    for (int i = tid; i < BPB * K; i += NTHR) {
        int j = i / K, kk = i - j * K;
        xs[j * K + kk] = x[(size_t)(b0 + j) * K + kk] * mk[j * TP + kk / C];
    }
    __syncthreads();

    const int w = tid >> 5, lane = tid & 31;

    // x2[b] = sum (m*x)^2  (mask binary => m^2 = m). Warps 0..3, one b each.
    if (w < BPB) {
        float s = 0.0f;
        for (int i = lane; i < K; i += 32) { float v = xs[w * K + i]; s = fmaf(v, v, s); }
#pragma unroll
        for (int o = 16; o; o >>= 1) s += __shfl_down_sync(0xffffffffu, s, o);
        if (lane == 0) x2s[w] = s;
    }

    const int p0 = w * 8;
    float axp[BPB][8], ap2[BPB][8];
#pragma unroll
    for (int j = 0; j < BPB; j++)
#pragma unroll
        for (int jp = 0; jp < 8; jp++) { axp[j][jp] = 0.0f; ap2[j][jp] = 0.0f; }

    // Main GEMM-like loop over K=3650 (xp term)
    for (int i = lane; i < K; i += 32) {
        float xv[BPB];
#pragma unroll
        for (int j = 0; j < BPB; j++) xv[j] = xs[j * K + i];
#pragma unroll
        for (int jp = 0; jp < 8; jp++) {
            float pv = __ldg(&proto[(size_t)(p0 + jp) * K + i]);
#pragma unroll
            for (int j = 0; j < BPB; j++)
                axp[j][jp] = fmaf(xv[j], pv, axp[j][jp]);
        }
    }

    // p2 term over T=365
    for (int t = lane; t < T; t += 32) {
        float mv[BPB];
#pragma unroll
        for (int j = 0; j < BPB; j++) mv[j] = mk[j * TP + t];
#pragma unroll
        for (int jp = 0; jp < 8; jp++) {
            float qv = g_q[(p0 + jp) * T + t];
#pragma unroll
            for (int j = 0; j < BPB; j++)
                ap2[j][jp] = fmaf(mv[j], qv, ap2[j][jp]);
        }
    }

    // Warp-reduce each accumulator, lane 0 stores partial distance
#pragma unroll
    for (int j = 0; j < BPB; j++)
#pragma unroll
        for (int jp = 0; jp < 8; jp++) {
            float v = axp[j][jp], u = ap2[j][jp];
#pragma unroll
            for (int o = 16; o; o >>= 1) {
                v += __shfl_down_sync(0xffffffffu, v, o);
                u += __shfl_down_sync(0xffffffffu, u, o);
            }
            if (lane == 0) ds[j * P + p0 + jp] = fmaf(-2.0f, v, u);
        }
    __syncthreads();

    // Finalize distances (+x2) and write out. 256 threads = 4*64.
    {
        int j = tid >> 6, p = tid & 63;
        float d = ds[j * P + p] + x2s[j];
        ds[j * P + p] = d;
        out[O2 + (size_t)(b0 + j) * P + p] = d;
    }
    __syncthreads();

    // Argmin (first-min tie-break, matching jnp.argmin)
    if (tid < BPB) {
        int j = tid;
        float best = ds[j * P]; int bi = 0;
#pragma unroll
        for (int p = 1; p < P; p++) {
            float v = ds[j * P + p];
            if (v < best) { best = v; bi = p; }
        }
        g_idx[b0 + j] = bi;
        out[O3 + b0 + j] = (float)bi;
    }
}

// ---------------------------------------------------------------------------
// Kernel 2: epilogue — gather output_seq, copy input_seq / mask / label
// ---------------------------------------------------------------------------
__global__ void epilogue_kernel(const float* __restrict__ x,
                                const float* __restrict__ mask,
                                const int* __restrict__ label,
                                const float* __restrict__ proto,
                                float* __restrict__ out) {
    const int gsz = gridDim.x * blockDim.x;
    const int g   = blockIdx.x * blockDim.x + threadIdx.x;

    // output_seq[b] = proto[idx[b]]  (row length 3650 => float2 vectorization)
    constexpr int K2 = K / 2;  // 1825
    const float2* pr2 = (const float2*)proto;
    float2* o0 = (float2*)out;
    for (int i = g; i < B * K2; i += gsz) {
        int b = i / K2;
        int r = i - b * K2;
        o0[i] = pr2[(size_t)g_idx[b] * K2 + r];
    }

    // input_seq copy (float4)
    const float4* x4 = (const float4*)x;
    float4* o1 = (float4*)(out + O1);
    for (int i = g; i < (B * K) / 4; i += gsz) o1[i] = x4[i];

    // mask copy (float4)
    const float4* m4 = (const float4*)mask;
    float4* o5 = (float4*)(out + O5);
    for (int i = g; i < (B * T) / 4; i += gsz) o5[i] = m4[i];

    // label (int -> float)
    for (int i = g; i < B; i += gsz) out[O4 + i] = (float)label[i];
}

// ---------------------------------------------------------------------------
extern "C" void kernel_launch(void* const* d_in, const int* in_sizes, int n_in,
                              void* d_out, int out_size) {
    (void)in_sizes; (void)n_in; (void)out_size;
    const float* x     = (const float*)d_in[0];
    const float* mask  = (const float*)d_in[1];
    const int*   label = (const int*)  d_in[2];
    const float* proto = (const float*)d_in[3];
    float* out = (float*)d_out;

    constexpr size_t SMEM = (size_t)(BPB * K + BPB * TP + BPB * P + BPB) * sizeof(float);
    cudaFuncSetAttribute(dist_kernel,
                         cudaFuncAttributeMaxDynamicSharedMemorySize, (int)SMEM);

    q_kernel<<<(P * T + 255) / 256, 256>>>(proto);
    dist_kernel<<<NBLK, NTHR, SMEM>>>(x, mask, proto, out);
    epilogue_kernel<<<592, 256>>>(x, mask, label, proto, out);
}

// round 2
// speedup vs baseline: 1.7335x; 1.7335x over previous
#include <cuda_runtime.h>

// Problem constants
constexpr int B = 512, T = 365, C = 10, P = 64;
constexpr int K  = T * C;       // 3650
constexpr int KE = K + T;       // 4015 (masked-x cols + mask cols)
constexpr int KP = 4096;        // padded K for GEMM
constexpr int NKC = 32;         // split-K chunks
constexpr int KC  = KP / NKC;   // 128 k per chunk

// Output layout (flattened tuple, all float32):
// [output_seq BK][input_seq BK][distances BP][indices B][label B][mask BT]
constexpr int O1 = B * K;
constexpr int O2 = O1 + B * K;
constexpr int O3 = O2 + B * P;
constexpr int O4 = O3 + B;
constexpr int O5 = O4 + B;

// Scratch (device globals: allocation-free)
__device__ float g_A[B * KP];    // [mask*x | mask | 0]
__device__ float g_Bm[P * KP];   // [-2*proto | q | 0]
__device__ float g_acc[B * P];   // GEMM accumulator (split-K partials)

// ---------------------------------------------------------------------------
// Kernel 0: build extended A and B matrices, zero the accumulator.
// ---------------------------------------------------------------------------
__global__ void prep_kernel(const float* __restrict__ x,
                            const float* __restrict__ mask,
                            const float* __restrict__ proto) {
    const int gid = blockIdx.x * blockDim.x + threadIdx.x;
    if (gid < B * KP) {
        const int b = gid >> 12, kk = gid & (KP - 1);
        float v = 0.0f;
        if (kk < K)       v = x[(size_t)b * K + kk] * mask[b * T + kk / C];
        else if (kk < KE) v = mask[b * T + (kk - K)];
        g_A[gid] = v;
    }
    if (gid < P * KP) {
        const int p = gid >> 12, kk = gid & (KP - 1);
        float v = 0.0f;
        if (kk < K) {
            v = -2.0f * proto[(size_t)p * K + kk];
        } else if (kk < KE) {
            const int t = kk - K;
            const float* pr = proto + (size_t)p * K + t * C;
            float s = 0.0f;
#pragma unroll
            for (int c = 0; c < C; c++) s = fmaf(pr[c], pr[c], s);
            v = s;
        }
        g_Bm[gid] = v;
    }
    if (gid < B * P) g_acc[gid] = 0.0f;
}

// ---------------------------------------------------------------------------
// Kernel 1: split-K SGEMM.  acc[b,p] += A[b, kc*128 : +128] . Bm[p, same]
// Grid: (8 b-tiles, 32 k-chunks). CTA computes a 64x64 C tile, 4x4 per thread.
// smem: double-buffered 64-k stages, [k][row] layout, row-dim padded to 68.
// ---------------------------------------------------------------------------
constexpr int PAD = 68;   // 272B row stride: 16B-aligned, conflict-light

#define AS(s, k, r) smA[((s) * 64 + (k)) * PAD + (r)]
#define BS(s, k, r) smB[((s) * 64 + (k)) * PAD + (r)]

__global__ __launch_bounds__(256) void gemm_kernel() {
    extern __shared__ float sm[];
    float* smA = sm;                    // 2 stages * 64 k * 68
    float* smB = sm + 2 * 64 * PAD;

    const int tid   = threadIdx.x;
    const int btile = blockIdx.x;       // 0..7
    const int kbase = blockIdx.y * KC;  // chunk start

    // ---- loader mapping: 16 float4 per row-group, 4 rows per thread
    const int k4    = tid & 15;         // float4 index within 64-k stage
    const int rbase = tid >> 4;         // 0..15
    const float* gA = g_A  + (size_t)(btile * 64) * KP + kbase + k4 * 4;
    const float* gB = g_Bm + (size_t)kbase + k4 * 4;

    float4 pa[4], pb[4];

    auto load_stage = [&](int s) {
#pragma unroll
        for (int r = 0; r < 4; r++) {
            const int row = r * 16 + rbase;
            pa[r] = *(const float4*)(gA + (size_t)row * KP + s * 64);
            pb[r] = *(const float4*)(gB + (size_t)row * KP + s * 64);
        }
    };
    auto store_stage = [&](int s) {
#pragma unroll
        for (int r = 0; r < 4; r++) {
            const int row = r * 16 + rbase;
#pragma unroll
            for (int i = 0; i < 4; i++) {
                AS(s, k4 * 4 + i, row) = ((const float*)&pa[r])[i];
                BS(s, k4 * 4 + i, row) = ((const float*)&pb[r])[i];
            }
        }
    };

    // ---- compute mapping
    const int tx = tid & 15;            // p quad
    const int ty = tid >> 4;            // b quad
    float acc[4][4] = {};

    auto compute = [&](int s) {
#pragma unroll 8
        for (int k = 0; k < 64; k++) {
            const float4 a = *(const float4*)&AS(s, k, ty * 4);
            const float4 b = *(const float4*)&BS(s, k, tx * 4);
            acc[0][0] = fmaf(a.x, b.x, acc[0][0]);
            acc[0][1] = fmaf(a.x, b.y, acc[0][1]);
            acc[0][2] = fmaf(a.x, b.z, acc[0][2]);
            acc[0][3] = fmaf(a.x, b.w, acc[0][3]);
            acc[1][0] = fmaf(a.y, b.x, acc[1][0]);
            acc[1][1] = fmaf(a.y, b.y, acc[1][1]);
            acc[1][2] = fmaf(a.y, b.z, acc[1][2]);
            acc[1][3] = fmaf(a.y, b.w, acc[1][3]);
            acc[2][0] = fmaf(a.z, b.x, acc[2][0]);
            acc[2][1] = fmaf(a.z, b.y, acc[2][1]);
            acc[2][2] = fmaf(a.z, b.z, acc[2][2]);
            acc[2][3] = fmaf(a.z, b.w, acc[2][3]);
            acc[3][0] = fmaf(a.w, b.x, acc[3][0]);
            acc[3][1] = fmaf(a.w, b.y, acc[3][1]);
            acc[3][2] = fmaf(a.w, b.z, acc[3][2]);
            acc[3][3] = fmaf(a.w, b.w, acc[3][3]);
        }
    };

    // chunk = 2 stages of 64 k, software pipelined
    load_stage(0);
    store_stage(0);
    __syncthreads();
    load_stage(1);          // prefetch stage 1 while computing stage 0
    compute(0);
    store_stage(1);
    __syncthreads();
    compute(1);

    // split-K accumulate (RED.F32, spread addresses)
    float* dst = g_acc + (size_t)(btile * 64 + ty * 4) * P + tx * 4;
#pragma unroll
    for (int i = 0; i < 4; i++)
#pragma unroll
        for (int j = 0; j < 4; j++)
            atomicAdd(&dst[i * P + j], acc[i][j]);
}

// ---------------------------------------------------------------------------
// Kernel 2: per-sample finalize. One CTA per b (512 CTAs x 128 threads):
// x2 reduce fused with input_seq copy, distances, argmin, gather, mask/label.
// ---------------------------------------------------------------------------
__global__ __launch_bounds__(128) void final_kernel(
    const float* __restrict__ x, const float* __restrict__ mask,
    const int* __restrict__ label, const float* __restrict__ proto,
    float* __restrict__ out) {
    __shared__ float mk[T];
    __shared__ float dist[P];
    __shared__ float wred[4];
    __shared__ int sidx;

    const int b = blockIdx.x, tid = threadIdx.x;

    // mask row -> smem + output
    for (int t = tid; t < T; t += 128) {
        const float m = mask[b * T + t];
        mk[t] = m;
        out[O5 + b * T + t] = m;
    }
    __syncthreads();

    // input_seq copy fused with x2 = sum m*x^2 (float2: rows are 8B-aligned)
    const float2* xr = (const float2*)(x + (size_t)b * K);
    float2* o1 = (float2*)(out + O1 + (size_t)b * K);
    float s = 0.0f;
    for (int i = tid; i < K / 2; i += 128) {
        const float2 v = xr[i];
        o1[i] = v;
        const float m0 = mk[(2 * i) / C];
        const float m1 = mk[(2 * i + 1) / C];
        s = fmaf(v.x * m0, v.x, s);
        s = fmaf(v.y * m1, v.y, s);
    }
#pragma unroll
    for (int o = 16; o; o >>= 1) s += __shfl_down_sync(0xffffffffu, s, o);
    if ((tid & 31) == 0) wred[tid >> 5] = s;
    __syncthreads();
    const float x2 = wred[0] + wred[1] + wred[2] + wred[3];

    // distances
    if (tid < P) {
        const float d = x2 + g_acc[b * P + tid];
        dist[tid] = d;
        out[O2 + (size_t)b * P + tid] = d;
    }
    __syncthreads();

    // argmin with first-min tie-break (matches jnp.argmin)
    if (tid < 32) {
        float v0 = dist[tid], v1 = dist[tid + 32];
        float v; int ix;
        if (v1 < v0) { v = v1; ix = tid + 32; } else { v = v0; ix = tid; }
#pragma unroll
        for (int o = 16; o; o >>= 1) {
            const float ov = __shfl_down_sync(0xffffffffu, v, o);
            const int   oi = __shfl_down_sync(0xffffffffu, ix, o);
            if (ov < v || (ov == v && oi < ix)) { v = ov; ix = oi; }
        }
        if (tid == 0) {
            sidx = ix;
            out[O3 + b] = (float)ix;
            out[O4 + b] = (float)label[b];
        }
    }
    __syncthreads();

    // gather selected prototype
    const float2* pr = (const float2*)(proto + (size_t)sidx * K);
    float2* o0 = (float2*)(out + (size_t)b * K);
    for (int i = tid; i < K / 2; i += 128) o0[i] = pr[i];
}

// ---------------------------------------------------------------------------
extern "C" void kernel_launch(void* const* d_in, const int* in_sizes, int n_in,
                              void* d_out, int out_size) {
    (void)in_sizes; (void)n_in; (void)out_size;
    const float* x     = (const float*)d_in[0];
    const float* mask  = (const float*)d_in[1];
    const int*   label = (const int*)  d_in[2];
    const float* proto = (const float*)d_in[3];
    float* out = (float*)d_out;

    constexpr size_t GSM = (size_t)2 * 2 * 64 * PAD * sizeof(float); // 69632 B
    cudaFuncSetAttribute(gemm_kernel,
                         cudaFuncAttributeMaxDynamicSharedMemorySize, (int)GSM);

    prep_kernel<<<(B * KP + 255) / 256, 256>>>(x, mask, proto);
    gemm_kernel<<<dim3(B / 64, NKC), 256, GSM>>>();
    final_kernel<<<B, 128>>>(x, mask, label, proto, out);
}

// round 4
// speedup vs baseline: 1.8445x; 1.0640x over previous
#include <cuda_runtime.h>

// Problem constants
constexpr int B = 512, T = 365, C = 10, P = 64;
constexpr int K  = T * C;       // 3650
constexpr int KE = K + T;       // 4015
constexpr int KP = 4096;        // padded K
constexpr int NKC = 32;         // split-K chunks
constexpr int KC  = KP / NKC;   // 128 k per chunk

// Output layout: [output_seq BK][input_seq BK][distances BP][indices B][label B][mask BT]
constexpr int O1 = B * K;
constexpr int O2 = O1 + B * K;
constexpr int O3 = O2 + B * P;
constexpr int O4 = O3 + B;
constexpr int O5 = O4 + B;

// Scratch
__device__ float g_Bm[P * KP];        // [-2*proto | q | 0]   (1 MB, L2)
__device__ float g_part[NKC * B * P]; // split-K partials     (4 MB, L2)

// ---------------------------------------------------------------------------
// Kernel 0: build B matrix only (vectorized). ~1us.
// ---------------------------------------------------------------------------
__global__ void prep_kernel(const float* __restrict__ proto) {
    const int gid = blockIdx.x * blockDim.x + threadIdx.x;
    constexpr int N1 = P * K / 2;   // float2 copies of -2*proto
    if (gid < N1) {
        const int p = gid / (K / 2), r = gid - p * (K / 2);
        const float2 v = *(const float2*)(proto + (size_t)p * K + 2 * r);
        *(float2*)(g_Bm + (size_t)p * KP + 2 * r) = make_float2(-2.f * v.x, -2.f * v.y);
    }
    if (gid < P * T) {              // q[p,t] = sum_c proto^2
        const int p = gid / T, t = gid - p * T;
        const float* pr = proto + (size_t)p * K + t * C;
        float s = 0.f;
#pragma unroll
        for (int c = 0; c < C; c += 2) {
            const float2 u = *(const float2*)(pr + c);
            s = fmaf(u.x, u.x, fmaf(u.y, u.y, s));
        }
        g_Bm[(size_t)p * KP + K + t] = s;
    }
    if (gid < P * (KP - KE)) {      // zero pad
        const int p = gid / (KP - KE), r = gid - p * (KP - KE);
        g_Bm[(size_t)p * KP + KE + r] = 0.f;
    }
}

// ---------------------------------------------------------------------------
// Kernel 1: fused split-K SGEMM.
//   A[b,kk] = kk<K ? x[b,kk]*mask[b,kk/C] : (kk<KE ? mask[b,kk-K] : 0)  (on the fly)
//   g_part[kc,b,p] = A[b, kc*128:+128] . Bm[p, same]
// Grid (4 btiles, 32 kchunks) = 128 CTAs. 128x64 C tile, 8x4 per thread.
// ---------------------------------------------------------------------------
constexpr int PADR = 132;   // smem A row-dim stride (float4-friendly)
constexpr int PADB = 68;

__global__ __launch_bounds__(256) void gemm_kernel(const float* __restrict__ x,
                                                   const float* __restrict__ mask) {
    extern __shared__ float sm[];
    float* smA = sm;                          // 2 stages * 64k * PADR
    float* smB = smA + 2 * 64 * PADR;         // 2 stages * 64k * PADB
    float* mT  = smB + 2 * 64 * PADB;         // 128 rows * 16 t

    const int tid   = threadIdx.x;
    const int b0    = blockIdx.x * 128;
    const int kbase = blockIdx.y * KC;
    const int t0    = kbase / C;

    // Per-chunk mask tile: t in [t0, t0+15] covers all x-region lookups.
    for (int i = tid; i < 128 * 16; i += 256) {
        const int r = i >> 4, tt = i & 15, t = t0 + tt;
        mT[i] = (t < T) ? mask[(b0 + r) * T + t] : 0.f;
    }
    __syncthreads();

    const int k4 = tid & 15;        // float4 slot within 64-k stage
    const int rA = tid >> 4;        // 0..15

    float4 va[8], vb[4];

    auto loadA = [&](int s) {
        const int kk = kbase + s * 64 + k4 * 4;
        if (kk + 3 < K) {  // fast path: pure x region
            const int tA = kk / C - t0, tB = (kk + 1) / C - t0;
            const int tC2 = (kk + 2) / C - t0, tD = (kk + 3) / C - t0;
#pragma unroll
            for (int i = 0; i < 8; i++) {
                const int row = rA + 16 * i;
                const float* xp = x + (size_t)(b0 + row) * K + kk;
                const float2 u = *(const float2*)xp;
                const float2 v = *(const float2*)(xp + 2);
                const float* m = mT + row * 16;
                va[i] = make_float4(u.x * m[tA], u.y * m[tB],
                                    v.x * m[tC2], v.y * m[tD]);
            }
        } else {           // boundary / mask-column / pad region
#pragma unroll
            for (int i = 0; i < 8; i++) {
                const int row = rA + 16 * i;
                float w[4];
#pragma unroll
                for (int j = 0; j < 4; j++) {
                    const int k = kk + j;
                    float v = 0.f;
                    if (k < K)
                        v = x[(size_t)(b0 + row) * K + k] * mT[row * 16 + (k / C - t0)];
                    else if (k < KE)
                        v = mask[(b0 + row) * T + (k - K)];
                    w[j] = v;
                }
                va[i] = make_float4(w[0], w[1], w[2], w[3]);
            }
        }
    };
    auto storeA = [&](int s) {
#pragma unroll
        for (int i = 0; i < 8; i++) {
            const int row = rA + 16 * i;
            float* dst = smA + (size_t)(s * 64 + k4 * 4) * PADR + row;
            dst[0] = va[i].x; dst[PADR] = va[i].y;
            dst[2 * PADR] = va[i].z; dst[3 * PADR] = va[i].w;
        }
    };
    auto loadB = [&](int s) {
        const int kk = kbase + s * 64 + k4 * 4;
#pragma unroll
        for (int i = 0; i < 4; i++)
            vb[i] = *(const float4*)(g_Bm + (size_t)(rA + 16 * i) * KP + kk);
    };
    auto storeB = [&](int s) {
#pragma unroll
        for (int i = 0; i < 4; i++) {
            const int p = rA + 16 * i;
            float* dst = smB + (size_t)(s * 64 + k4 * 4) * PADB + p;
            dst[0] = vb[i].x; dst[PADB] = vb[i].y;
            dst[2 * PADB] = vb[i].z; dst[3 * PADB] = vb[i].w;
        }
    };

    const int tx = tid & 15;        // p quad
    const int ty = tid >> 4;        // b octet
    float acc[8][4] = {};

    auto compute = [&](int s) {
#pragma unroll 4
        for (int k = 0; k < 64; k++) {
            const float* ak = smA + (size_t)(s * 64 + k) * PADR + ty * 8;
            const float4 a0 = *(const float4*)ak;
            const float4 a1 = *(const float4*)(ak + 4);
            const float4 b  = *(const float4*)(smB + (size_t)(s * 64 + k) * PADB + tx * 4);
            const float av[8] = {a0.x, a0.y, a0.z, a0.w, a1.x, a1.y, a1.z, a1.w};
#pragma unroll
            for (int i = 0; i < 8; i++) {
                acc[i][0] = fmaf(av[i], b.x, acc[i][0]);
                acc[i][1] = fmaf(av[i], b.y, acc[i][1]);
                acc[i][2] = fmaf(av[i], b.z, acc[i][2]);
                acc[i][3] = fmaf(av[i], b.w, acc[i][3]);
            }
        }
    };

    // 2-stage software pipeline over the 128-k chunk
    loadA(0); loadB(0);
    storeA(0); storeB(0);
    __syncthreads();
    loadA(1); loadB(1);
    compute(0);
    storeA(1); storeB(1);
    __syncthreads();
    compute(1);

    // plain STG partials (no atomics)
    float* dst = g_part + ((size_t)blockIdx.y * B + b0 + ty * 8) * P + tx * 4;
#pragma unroll
    for (int i = 0; i < 8; i++)
        *(float4*)(dst + (size_t)i * P) = make_float4(acc[i][0], acc[i][1],
                                                      acc[i][2], acc[i][3]);
}

// ---------------------------------------------------------------------------
// Kernel 2: per-sample finalize (one CTA per b): split-K reduce, x2 fused
// with input_seq copy, distances, argmin, gather, mask/label.
// ---------------------------------------------------------------------------
__global__ __launch_bounds__(128) void final_kernel(
    const float* __restrict__ x, const float* __restrict__ mask,
    const int* __restrict__ label, const float* __restrict__ proto,
    float* __restrict__ out) {
    __shared__ float mk[T];
    __shared__ float dist[P];
    __shared__ float wred[4];
    __shared__ int sidx;

    const int b = blockIdx.x, tid = threadIdx.x;

    for (int t = tid; t < T; t += 128) {
        const float m = mask[b * T + t];
        mk[t] = m;
        out[O5 + b * T + t] = m;
    }
    __syncthreads();

    // input_seq copy fused with x2 = sum m*x^2
    const float2* xr = (const float2*)(x + (size_t)b * K);
    float2* o1 = (float2*)(out + O1 + (size_t)b * K);
    float s = 0.f;
    for (int i = tid; i < K / 2; i += 128) {
        const float2 v = xr[i];
        o1[i] = v;
        s = fmaf(v.x * mk[(2 * i) / C], v.x, s);
        s = fmaf(v.y * mk[(2 * i + 1) / C], v.y, s);
    }
#pragma unroll
    for (int o = 16; o; o >>= 1) s += __shfl_down_sync(0xffffffffu, s, o);
    if ((tid & 31) == 0) wred[tid >> 5] = s;
    __syncthreads();
    const float x2 = wred[0] + wred[1] + wred[2] + wred[3];

    // split-K reduce + distances
    if (tid < P) {
        float d0 = 0.f, d1 = 0.f, d2 = 0.f, d3 = 0.f;
#pragma unroll
        for (int kc = 0; kc < NKC; kc += 4) {
            d0 += g_part[(size_t)(kc + 0) * B * P + b * P + tid];
            d1 += g_part[(size_t)(kc + 1) * B * P + b * P + tid];
            d2 += g_part[(size_t)(kc + 2) * B * P + b * P + tid];
            d3 += g_part[(size_t)(kc + 3) * B * P + b * P + tid];
        }
        const float d = x2 + ((d0 + d1) + (d2 + d3));
        dist[tid] = d;
        out[O2 + (size_t)b * P + tid] = d;
    }
    __syncthreads();

    // argmin, first-min tie-break
    if (tid < 32) {
        float v0 = dist[tid], v1 = dist[tid + 32];
        float v; int ix;
        if (v1 < v0) { v = v1; ix = tid + 32; } else { v = v0; ix = tid; }
#pragma unroll
        for (int o = 16; o; o >>= 1) {
            const float ov = __shfl_down_sync(0xffffffffu, v, o);
            const int   oi = __shfl_down_sync(0xffffffffu, ix, o);
            if (ov < v || (ov == v && oi < ix)) { v = ov; ix = oi; }
        }
        if (tid == 0) {
            sidx = ix;
            out[O3 + b] = (float)ix;
            out[O4 + b] = (float)label[b];
        }
    }
    __syncthreads();

    const float2* pr = (const float2*)(proto + (size_t)sidx * K);
    float2* o0 = (float2*)(out + (size_t)b * K);
    for (int i = tid; i < K / 2; i += 128) o0[i] = pr[i];
}

// ---------------------------------------------------------------------------
extern "C" void kernel_launch(void* const* d_in, const int* in_sizes, int n_in,
                              void* d_out, int out_size) {
    (void)in_sizes; (void)n_in; (void)out_size;
    const float* x     = (const float*)d_in[0];
    const float* mask  = (const float*)d_in[1];
    const int*   label = (const int*)  d_in[2];
    const float* proto = (const float*)d_in[3];
    float* out = (float*)d_out;

    constexpr size_t GSM =
        (size_t)(2 * 64 * PADR + 2 * 64 * PADB + 128 * 16) * sizeof(float);
    cudaFuncSetAttribute(gemm_kernel,
                         cudaFuncAttributeMaxDynamicSharedMemorySize, (int)GSM);

    prep_kernel<<<(P * K / 2 + 255) / 256, 256>>>(proto);
    gemm_kernel<<<dim3(B / 128, NKC), 256, GSM>>>(x, mask);
    final_kernel<<<B, 128>>>(x, mask, label, proto, out);
}

// round 6
// speedup vs baseline: 1.9728x; 1.0696x over previous
#include <cuda_runtime.h>

// Problem constants
constexpr int B = 512, T = 365, C = 10, P = 64;
constexpr int K  = T * C;       // 3650
constexpr int KE = K + T;       // 4015
constexpr int KP = 4096;        // padded K
constexpr int NKC = 32;         // split-K chunks
constexpr int KC  = KP / NKC;   // 128 k per chunk

// Output layout: [output_seq BK][input_seq BK][distances BP][indices B][label B][mask BT]
constexpr int O1 = B * K;
constexpr int O2 = O1 + B * K;
constexpr int O3 = O2 + B * P;
constexpr int O4 = O3 + B;
constexpr int O5 = O4 + B;

// Scratch
__device__ float g_Bm[P * KP];        // [-2*proto | q | 0]   (1 MB, L2)
__device__ float g_part[NKC * B * P]; // split-K partials     (4 MB, L2)

// ---------------------------------------------------------------------------
// Kernel 0: build g_Bm. One CTA per prototype; row staged in smem.
// ---------------------------------------------------------------------------
__global__ __launch_bounds__(256) void prep_kernel(const float* __restrict__ proto) {
    __shared__ float row[K];
    const int p = blockIdx.x, tid = threadIdx.x;

    // stage proto row (float2; rows are 8B-aligned since K even)
    const float2* src = (const float2*)(proto + (size_t)p * K);
    for (int i = tid; i < K / 2; i += 256) {
        const float2 v = src[i];
        row[2 * i] = v.x; row[2 * i + 1] = v.y;
    }
    __syncthreads();

    float* dstR = g_Bm + (size_t)p * KP;

    // -2*row (float4; dstR is 16B-aligned)
    for (int i = tid; i < K / 4; i += 256) {  // 912 float4 (covers 3648)
        float4 v;
        v.x = -2.f * row[4 * i];     v.y = -2.f * row[4 * i + 1];
        v.z = -2.f * row[4 * i + 2]; v.w = -2.f * row[4 * i + 3];
        *(float4*)(dstR + 4 * i) = v;
    }
    if (tid < 2) dstR[3648 + tid] = -2.f * row[3648 + tid];

    // q[t] = sum_c row[t*C+c]^2
    for (int t = tid; t < T; t += 256) {
        const float* r = row + t * C;
        float s = 0.f;
#pragma unroll
        for (int c = 0; c < C; c++) s = fmaf(r[c], r[c], s);
        dstR[K + t] = s;
    }
    // zero pad
    for (int i = KE + tid; i < KP; i += 256) dstR[i] = 0.f;
}

// ---------------------------------------------------------------------------
// Kernel 1: fused split-K SGEMM.
//   A[b,kk] = kk<K ? x[b,kk]*mask[b,kk/C] : (kk<KE ? mask[b,kk-K] : 0)
//   g_part[kc,b,p] = A[b, kc*128:+128] . Bm[p, same]
// Grid (4 btiles, 32 kchunks) = 128 CTAs. 128x64 C tile, 8x4 per thread.
// smem [k][row] with ODD padding (129/65): 2-way store conflicts max,
// scalar compute loads (A broadcast 1-wf, B 2-wf).
// ---------------------------------------------------------------------------
constexpr int PADR = 129;
constexpr int PADB = 65;

__global__ __launch_bounds__(256) void gemm_kernel(const float* __restrict__ x,
                                                   const float* __restrict__ mask) {
    extern __shared__ float sm[];
    float* smA = sm;                          // 2 stages * 64k * PADR
    float* smB = smA + 2 * 64 * PADR;         // 2 stages * 64k * PADB
    float* mT  = smB + 2 * 64 * PADB;         // 128 rows * 16 t

    const int tid   = threadIdx.x;
    const int b0    = blockIdx.x * 128;
    const int kbase = blockIdx.y * KC;
    const int t0    = kbase / C;

    for (int i = tid; i < 128 * 16; i += 256) {
        const int r = i >> 4, tt = i & 15, t = t0 + tt;
        mT[i] = (t < T) ? mask[(b0 + r) * T + t] : 0.f;
    }
    __syncthreads();

    const int k4 = tid & 15;        // float4 slot within 64-k stage
    const int rA = tid >> 4;        // 0..15

    float4 va[8], vb[4];

    auto loadA = [&](int s) {
        const int kk = kbase + s * 64 + k4 * 4;
        if (kk + 3 < K) {
            const int tA = kk / C - t0, tB = (kk + 1) / C - t0;
            const int tC2 = (kk + 2) / C - t0, tD = (kk + 3) / C - t0;
#pragma unroll
            for (int i = 0; i < 8; i++) {
                const int row = rA + 16 * i;
                const float* xp = x + (size_t)(b0 + row) * K + kk;
                const float2 u = *(const float2*)xp;
                const float2 v = *(const float2*)(xp + 2);
                const float* m = mT + row * 16;
                va[i] = make_float4(u.x * m[tA], u.y * m[tB],
                                    v.x * m[tC2], v.y * m[tD]);
            }
        } else {
#pragma unroll
            for (int i = 0; i < 8; i++) {
                const int row = rA + 16 * i;
                float w[4];
#pragma unroll
                for (int j = 0; j < 4; j++) {
                    const int k = kk + j;
                    float v = 0.f;
                    if (k < K)
                        v = x[(size_t)(b0 + row) * K + k] * mT[row * 16 + (k / C - t0)];
                    else if (k < KE)
                        v = mask[(b0 + row) * T + (k - K)];
                    w[j] = v;
                }
                va[i] = make_float4(w[0], w[1], w[2], w[3]);
            }
        }
    };
    auto storeA = [&](int s) {
#pragma unroll
        for (int i = 0; i < 8; i++) {
            const int row = rA + 16 * i;
            float* dst = smA + (size_t)(s * 64 + k4 * 4) * PADR + row;
            dst[0] = va[i].x; dst[PADR] = va[i].y;
            dst[2 * PADR] = va[i].z; dst[3 * PADR] = va[i].w;
        }
    };
    auto loadB = [&](int s) {
        const int kk = kbase + s * 64 + k4 * 4;
#pragma unroll
        for (int i = 0; i < 4; i++)
            vb[i] = *(const float4*)(g_Bm + (size_t)(rA + 16 * i) * KP + kk);
    };
    auto storeB = [&](int s) {
#pragma unroll
        for (int i = 0; i < 4; i++) {
            const int p = rA + 16 * i;
            float* dst = smB + (size_t)(s * 64 + k4 * 4) * PADB + p;
            dst[0] = vb[i].x; dst[PADB] = vb[i].y;
            dst[2 * PADB] = vb[i].z; dst[3 * PADB] = vb[i].w;
        }
    };

    const int tx = tid & 15;        // p quad (contiguous: p = tx*4+j)
    const int ty = tid >> 4;        // b octet (rows ty*8..+7)
    float acc[8][4] = {};

    auto compute = [&](int s) {
#pragma unroll 4
        for (int k = 0; k < 64; k++) {
            const float* ak = smA + (size_t)(s * 64 + k) * PADR + ty * 8;
            const float* bk = smB + (size_t)(s * 64 + k) * PADB + tx * 4;
            float av[8], b[4];
#pragma unroll
            for (int i = 0; i < 8; i++) av[i] = ak[i];   // broadcast LDS
#pragma unroll
            for (int j = 0; j < 4; j++) b[j] = bk[j];
#pragma unroll
            for (int i = 0; i < 8; i++) {
                acc[i][0] = fmaf(av[i], b[0], acc[i][0]);
                acc[i][1] = fmaf(av[i], b[1], acc[i][1]);
                acc[i][2] = fmaf(av[i], b[2], acc[i][2]);
                acc[i][3] = fmaf(av[i], b[3], acc[i][3]);
            }
        }
    };

    // 2-stage pipeline over the 128-k chunk
    loadA(0); loadB(0);
    storeA(0); storeB(0);
    __syncthreads();
    loadA(1); loadB(1);
    compute(0);
    storeA(1); storeB(1);
    __syncthreads();
    compute(1);

    float* dst = g_part + ((size_t)blockIdx.y * B + b0 + ty * 8) * P + tx * 4;
#pragma unroll
    for (int i = 0; i < 8; i++)
        *(float4*)(dst + (size_t)i * P) = make_float4(acc[i][0], acc[i][1],
                                                      acc[i][2], acc[i][3]);
}

// ---------------------------------------------------------------------------
// Kernel 2: per-sample finalize (one CTA per b).
// ---------------------------------------------------------------------------
__global__ __launch_bounds__(128) void final_kernel(
    const float* __restrict__ x, const float* __restrict__ mask,
    const int* __restrict__ label, const float* __restrict__ proto,
    float* __restrict__ out) {
    __shared__ float mk[T];
    __shared__ float dist[P];
    __shared__ float half1[P];
    __shared__ float wred[4];
    __shared__ int sidx;

    const int b = blockIdx.x, tid = threadIdx.x;

    for (int t = tid; t < T; t += 128) {
        const float m = mask[b * T + t];
        mk[t] = m;
        out[O5 + b * T + t] = m;
    }

    // split-K partial reduce: all 128 threads (p = tid&63, kc half = tid>>6)
    {
        const int p = tid & 63, h = tid >> 6;
        float d0 = 0.f, d1 = 0.f;
#pragma unroll
        for (int kc = 16 * h; kc < 16 * h + 16; kc += 2) {
            d0 += g_part[(size_t)kc * B * P + b * P + p];
            d1 += g_part[(size_t)(kc + 1) * B * P + b * P + p];
        }
        if (h == 0) dist[p] = d0 + d1; else half1[p] = d0 + d1;
    }
    __syncthreads();

    // input_seq copy fused with x2 = sum m*x^2
    const float2* xr = (const float2*)(x + (size_t)b * K);
    float2* o1 = (float2*)(out + O1 + (size_t)b * K);
    float s = 0.f;
    for (int i = tid; i < K / 2; i += 128) {
        const float2 v = xr[i];
        o1[i] = v;
        s = fmaf(v.x * mk[(2 * i) / C], v.x, s);
        s = fmaf(v.y * mk[(2 * i + 1) / C], v.y, s);
    }
#pragma unroll
    for (int o = 16; o; o >>= 1) s += __shfl_down_sync(0xffffffffu, s, o);
    if ((tid & 31) == 0) wred[tid >> 5] = s;
    __syncthreads();
    const float x2 = wred[0] + wred[1] + wred[2] + wred[3];

    if (tid < P) {
        const float d = x2 + dist[tid] + half1[tid];
        dist[tid] = d;
        out[O2 + (size_t)b * P + tid] = d;
    }
    __syncthreads();

    // argmin, first-min tie-break (matches jnp.argmin)
    if (tid < 32) {
        float v0 = dist[tid], v1 = dist[tid + 32];
        float v; int ix;
        if (v1 < v0) { v = v1; ix = tid + 32; } else { v = v0; ix = tid; }
#pragma unroll
        for (int o = 16; o; o >>= 1) {
            const float ov = __shfl_down_sync(0xffffffffu, v, o);
            const int   oi = __shfl_down_sync(0xffffffffu, ix, o);
            if (ov < v || (ov == v && oi < ix)) { v = ov; ix = oi; }
        }
        if (tid == 0) {
            sidx = ix;
            out[O3 + b] = (float)ix;
            out[O4 + b] = (float)label[b];
        }
    }
    __syncthreads();

    const float2* pr = (const float2*)(proto + (size_t)sidx * K);
    float2* o0 = (float2*)(out + (size_t)b * K);
    for (int i = tid; i < K / 2; i += 128) o0[i] = pr[i];
}

// ---------------------------------------------------------------------------
extern "C" void kernel_launch(void* const* d_in, const int* in_sizes, int n_in,
                              void* d_out, int out_size) {
    (void)in_sizes; (void)n_in; (void)out_size;
    const float* x     = (const float*)d_in[0];
    const float* mask  = (const float*)d_in[1];
    const int*   label = (const int*)  d_in[2];
    const float* proto = (const float*)d_in[3];
    float* out = (float*)d_out;

    constexpr size_t GSM =
        (size_t)(2 * 64 * PADR + 2 * 64 * PADB + 128 * 16) * sizeof(float);
    cudaFuncSetAttribute(gemm_kernel,
                         cudaFuncAttributeMaxDynamicSharedMemorySize, (int)GSM);

    prep_kernel<<<P, 256>>>(proto);
    gemm_kernel<<<dim3(B / 128, NKC), 256, GSM>>>(x, mask);
    final_kernel<<<B, 128>>>(x, mask, label, proto, out);
}